// round 15
// baseline (speedup 1.0000x reference)
#include <cuda_runtime.h>
#include <cuda_bf16.h>

// 3D RoPE apply:
//   x: (1, S, N=16, D=128) fp32, S = f*h*w (= 32760)
//   freqs_cos/sin: (1024, 64) fp32, cols [0,22)=F, [22,43)=H, [43,64)=W
//   seq pos s -> (fi, hi, wi); pair c: row = fi (c<22) | hi (c<43) | wi
//   out pair: (xr*cos - xi*sin, xr*sin + xi*cos)
//
// R14: best-measured structure (R9: SPB=8, x-loads front-batched before smem
// staging of packed {c0,s0,c1,s1} tables) with ONE change: x loads use
// __ldcg (L2-only, bypass L1). The zero-reuse x stream no longer thrashes
// L1, so the heavily-reused 256B table rows stay L1-resident and the
// barrier-critical staging loads hit at ~32 cyc instead of ~234.

#define NHEADS 16
#define DDIM   128
#define CPAIRS 64                        // D/2
#define VEC_PER_S (NHEADS * DDIM / 4)    // 512 float4 per seq position
#define SPB 8                            // seq positions per block
#define THREADS VEC_PER_S

template <bool GUARD>
__global__ __launch_bounds__(THREADS, 2)
void rope3d_kernel(const float4* __restrict__ x,
                   const float*  __restrict__ fcos,
                   const float*  __restrict__ fsin,
                   const int*    __restrict__ p_h,
                   const int*    __restrict__ p_w,
                   float4*       __restrict__ out,
                   int s_total)
{
    const int s0 = blockIdx.x * SPB;
    const int t  = threadIdx.x;

    // tab[k][p] = {cos[2p], sin[2p], cos[2p+1], sin[2p+1]} for position s0+k
    __shared__ float4 tab[SPB][CPAIRS / 2];

    // ---- Front-batch ALL 8 x-loads, L2-only (keep L1 for the tables) ----
    const int base = s0 * VEC_PER_S + t;
    float4 v[SPB];
#pragma unroll
    for (int k = 0; k < SPB; ++k) {
        if (!GUARD || (s0 + k < s_total))
            v[k] = __ldcg(&x[base + k * VEC_PER_S]);
    }

    // ---- Stage SPB rows of cos/sin, interleaved (512 threads cover 8x64) ----
    {
        const int k = t >> 6;        // position within block (0..7)
        const int c = t & 63;        // channel pair (0..63)
        const int s = s0 + k;
        if (!GUARD || (s < s_total)) {
            const int h   = *p_h;
            const int w   = *p_w;
            const int hw  = h * w;
            const int fi  = s / hw;
            const int rem = s - fi * hw;
            const int hi  = rem / w;
            const int wi  = rem - hi * w;
            const int pos = (c < 22) ? fi : ((c < 43) ? hi : wi);
            const float cv = __ldg(&fcos[pos * CPAIRS + c]);
            const float sv = __ldg(&fsin[pos * CPAIRS + c]);
            float* dst = &tab[k][c >> 1].x;      // word base of this float4
            dst[(c & 1) * 2]     = cv;
            dst[(c & 1) * 2 + 1] = sv;
        }
    }
    __syncthreads();

    const int p = t & 31;            // pair-group index of this thread's float4

#pragma unroll
    for (int k = 0; k < SPB; ++k) {
        if (GUARD && (s0 + k >= s_total)) break;
        const float4 cs = tab[k][p];             // {c0, s0, c1, s1}
        float4 o;
        o.x = fmaf(v[k].x, cs.x, -v[k].y * cs.y);
        o.y = fmaf(v[k].x, cs.y,  v[k].y * cs.x);
        o.z = fmaf(v[k].z, cs.z, -v[k].w * cs.w);
        o.w = fmaf(v[k].z, cs.w,  v[k].w * cs.z);
        out[base + k * VEC_PER_S] = o;
    }
}

extern "C" void kernel_launch(void* const* d_in, const int* in_sizes, int n_in,
                              void* d_out, int out_size)
{
    const float4* x    = (const float4*)d_in[0];
    const float*  fcos = (const float*)d_in[1];
    const float*  fsin = (const float*)d_in[2];
    const int* p_h = (const int*)d_in[4];
    const int* p_w = (const int*)d_in[5];
    float4* out = (float4*)d_out;

    const int s_total = in_sizes[0] / (NHEADS * DDIM);   // 32760

    if (s_total % SPB == 0) {
        rope3d_kernel<false><<<s_total / SPB, THREADS>>>(
            x, fcos, fsin, p_h, p_w, out, s_total);
    } else {
        rope3d_kernel<true><<<(s_total + SPB - 1) / SPB, THREADS>>>(
            x, fcos, fsin, p_h, p_w, out, s_total);
    }
}

// round 16
// speedup vs baseline: 1.0998x; 1.0998x over previous
#include <cuda_runtime.h>
#include <cuda_bf16.h>

// 3D RoPE apply:
//   x: (1, S, N=16, D=128) fp32, S = f*h*w (= 32760)
//   freqs_cos/sin: (1024, 64) fp32, cols [0,22)=F, [22,43)=H, [43,64)=W
//   seq pos s -> (fi, hi, wi); pair c: row = fi (c<22) | hi (c<43) | wi
//   out pair: (xr*cos - xi*sin, xr*sin + xi*cos)
//
// FINAL (R9 structure, best measured: kernel 75.07us, 6.40 TB/s, DRAM 80.8%):
//   - SPB=8 positions/block, 512 threads, 2 CTAs/SM
//   - all 8 x LDG.128 front-batched BEFORE table staging, so they are in
//     flight across the staging loads + barrier (MLP=8 per thread)
//   - cos/sin staged in smem packed as float4 {c0,s0,c1,s1}: 1 LDS.128 per
//     position in the hot loop
//   - DEFAULT cache policy everywhere (all non-default qualifiers measured
//     as regressions on sm_103a: __ldcs/__stcs R8, persistent R10, __ldcg R14)
// Exploration showed a hard plateau at ~6.4 TB/s = mixed r/w HBM ceiling.

#define NHEADS 16
#define DDIM   128
#define CPAIRS 64                        // D/2
#define VEC_PER_S (NHEADS * DDIM / 4)    // 512 float4 per seq position
#define SPB 8                            // seq positions per block
#define THREADS VEC_PER_S

template <bool GUARD>
__global__ __launch_bounds__(THREADS, 2)
void rope3d_kernel(const float4* __restrict__ x,
                   const float*  __restrict__ fcos,
                   const float*  __restrict__ fsin,
                   const int*    __restrict__ p_h,
                   const int*    __restrict__ p_w,
                   float4*       __restrict__ out,
                   int s_total)
{
    const int s0 = blockIdx.x * SPB;
    const int t  = threadIdx.x;

    // tab[k][p] = {cos[2p], sin[2p], cos[2p+1], sin[2p+1]} for position s0+k
    __shared__ float4 tab[SPB][CPAIRS / 2];

    // ---- Front-batch ALL 8 x-loads (in flight over staging + barrier) ----
    const int base = s0 * VEC_PER_S + t;
    float4 v[SPB];
#pragma unroll
    for (int k = 0; k < SPB; ++k) {
        if (!GUARD || (s0 + k < s_total))
            v[k] = x[base + k * VEC_PER_S];
    }

    // ---- Stage SPB rows of cos/sin, interleaved (512 threads cover 8x64) ----
    {
        const int k = t >> 6;        // position within block (0..7)
        const int c = t & 63;        // channel pair (0..63)
        const int s = s0 + k;
        if (!GUARD || (s < s_total)) {
            const int h   = *p_h;
            const int w   = *p_w;
            const int hw  = h * w;
            const int fi  = s / hw;
            const int rem = s - fi * hw;
            const int hi  = rem / w;
            const int wi  = rem - hi * w;
            const int pos = (c < 22) ? fi : ((c < 43) ? hi : wi);
            const float cv = __ldg(&fcos[pos * CPAIRS + c]);
            const float sv = __ldg(&fsin[pos * CPAIRS + c]);
            float* dst = &tab[k][c >> 1].x;      // word base of this float4
            dst[(c & 1) * 2]     = cv;
            dst[(c & 1) * 2 + 1] = sv;
        }
    }
    __syncthreads();

    const int p = t & 31;            // pair-group index of this thread's float4

#pragma unroll
    for (int k = 0; k < SPB; ++k) {
        if (GUARD && (s0 + k >= s_total)) break;
        const float4 cs = tab[k][p];             // {c0, s0, c1, s1}
        float4 o;
        o.x = fmaf(v[k].x, cs.x, -v[k].y * cs.y);
        o.y = fmaf(v[k].x, cs.y,  v[k].y * cs.x);
        o.z = fmaf(v[k].z, cs.z, -v[k].w * cs.w);
        o.w = fmaf(v[k].z, cs.w,  v[k].w * cs.z);
        out[base + k * VEC_PER_S] = o;
    }
}

extern "C" void kernel_launch(void* const* d_in, const int* in_sizes, int n_in,
                              void* d_out, int out_size)
{
    const float4* x    = (const float4*)d_in[0];
    const float*  fcos = (const float*)d_in[1];
    const float*  fsin = (const float*)d_in[2];
    const int* p_h = (const int*)d_in[4];
    const int* p_w = (const int*)d_in[5];
    float4* out = (float4*)d_out;

    const int s_total = in_sizes[0] / (NHEADS * DDIM);   // 32760

    if (s_total % SPB == 0) {
        rope3d_kernel<false><<<s_total / SPB, THREADS>>>(
            x, fcos, fsin, p_h, p_w, out, s_total);
    } else {
        rope3d_kernel<true><<<(s_total + SPB - 1) / SPB, THREADS>>>(
            x, fcos, fsin, p_h, p_w, out, s_total);
    }
}